// round 9
// baseline (speedup 1.0000x reference)
#include <cuda_runtime.h>
#include <cuda_fp16.h>
#include <cstdint>

#define N_NODES 50000
#define N_EDGES 600000
#define DIM     128
#define N_REL   10
#define LN_EPS  1e-5f
#define HSTRIDE 136      // padded smem row stride in halves (272 B)

#define NKEYS   500000   // N_NODES * N_REL
#define SCAN2B  1954     // ceil(NKEYS/256)
#define TILES   391      // ceil(50000/128)
#define WH_ELEMS (11 * DIM * DIM)
#define XH_ELEMS (N_NODES * 16)

// ---------------- device scratch ----------------
__device__ int    g_idx64;
__device__ int    g_rp2[NKEYS + 1];     // hist counters -> rowptr by (dst*10+rel)
__device__ int    g_fill2[NKEYS];
__device__ int    g_bsum2[SCAN2B];
__device__ int    g_boff2[SCAN2B];
__device__ int    g_edge[N_EDGES];      // src, sorted by (dst, rel)
__device__ __half g_wh[11 * DIM * DIM]; // [rel][k][o] fp16 (rel 10 = self)
__device__ __half g_xh[(size_t)N_NODES * DIM];   // x fp16

// ---------------- helpers ----------------
#define CP_ASYNC16(dst, src, sz) \
    asm volatile("cp.async.cg.shared.global [%0], [%1], 16, %2;" \
                 :: "r"(dst), "l"(src), "r"(sz))
#define CP_COMMIT() asm volatile("cp.async.commit_group;")
#define CP_WAIT0()  asm volatile("cp.async.wait_group 0;")

__device__ __forceinline__ uint32_t smem_u32(const void* p) {
    uint32_t a;
    asm("{ .reg .u64 t; cvta.to.shared.u64 t, %1; cvt.u32.u64 %0, t; }" : "=r"(a) : "l"(p));
    return a;
}
__device__ __forceinline__ void ldm_x4(uint32_t r[4], uint32_t addr) {
    asm volatile("ldmatrix.sync.aligned.m8n8.x4.shared.b16 {%0,%1,%2,%3}, [%4];"
        : "=r"(r[0]), "=r"(r[1]), "=r"(r[2]), "=r"(r[3]) : "r"(addr));
}
__device__ __forceinline__ void ldm_x4_t(uint32_t r[4], uint32_t addr) {
    asm volatile("ldmatrix.sync.aligned.m8n8.x4.trans.shared.b16 {%0,%1,%2,%3}, [%4];"
        : "=r"(r[0]), "=r"(r[1]), "=r"(r[2]), "=r"(r[3]) : "r"(addr));
}
__device__ __forceinline__ void mma_f16(float d[4], const uint32_t a[4],
                                        const uint32_t b[2]) {
    asm volatile(
        "mma.sync.aligned.m16n8k16.row.col.f32.f16.f16.f32 "
        "{%0,%1,%2,%3}, {%4,%5,%6,%7}, {%8,%9}, {%0,%1,%2,%3};\n"
        : "+f"(d[0]), "+f"(d[1]), "+f"(d[2]), "+f"(d[3])
        : "r"(a[0]), "r"(a[1]), "r"(a[2]), "r"(a[3]), "r"(b[0]), "r"(b[1]));
}
__device__ __forceinline__ int load_idx(const void* p, long long i, int is64) {
    return is64 ? (int)((const long long*)p)[i] : ((const int*)p)[i];
}

// ---------------- kernel 0: zero hist counters + dtype detect ----------------
__global__ void detect_zero_kernel(const unsigned int* ew) {
    int i = blockIdx.x * blockDim.x + threadIdx.x;
    if (i <= NKEYS) g_rp2[i] = 0;
    if (blockIdx.x == 0) {
        __shared__ unsigned int any;
        if (threadIdx.x == 0) any = 0u;
        __syncthreads();
        unsigned int v = 0;
        #pragma unroll
        for (int t = 0; t < 4; t++) v |= ew[((threadIdx.x * 4 + t) << 1) + 1];
        if (v) atomicOr(&any, 1u);
        __syncthreads();
        if (threadIdx.x == 0) g_idx64 = (any == 0u) ? 1 : 0;
    }
}

// ---------------- kernel 1: fp16 convert (weights + x) ----------------
__global__ void prep_convert_kernel(const float* __restrict__ relW,
                                    const float* __restrict__ w_self,
                                    const float* __restrict__ x) {
    int i = blockIdx.x * blockDim.x + threadIdx.x;
    if (i < WH_ELEMS) {
        int r = i >> 14;
        int j = i & 16383;                 // j = k*128 + o
        float v;
        if (r < N_REL) v = relW[(size_t)r * DIM * DIM + j];            // native [k][o]
        else { int k = j >> 7, o = j & 127; v = w_self[o * DIM + k]; } // [o][k]->[k][o]
        g_wh[i] = __float2half_rn(v);
    } else {
        int j = i - WH_ELEMS;
        if (j < XH_ELEMS) {
            const float4* src = (const float4*)x + j * 2;
            float4 a = src[0], b = src[1];
            __half2 h0 = __floats2half2_rn(a.x, a.y);
            __half2 h1 = __floats2half2_rn(a.z, a.w);
            __half2 h2 = __floats2half2_rn(b.x, b.y);
            __half2 h3 = __floats2half2_rn(b.z, b.w);
            uint4 pack;
            pack.x = *(uint32_t*)&h0; pack.y = *(uint32_t*)&h1;
            pack.z = *(uint32_t*)&h2; pack.w = *(uint32_t*)&h3;
            ((uint4*)g_xh)[j] = pack;
        }
    }
}

// ---------------- kernel 2: histogram over (dst*10+rel) ----------------
__global__ void hist_kernel(const void* ei, const void* etype) {
    int e = blockIdx.x * blockDim.x + threadIdx.x;
    if (e >= N_EDGES) return;
    int is64 = g_idx64;
    int dst = load_idx(ei, (long long)N_EDGES + e, is64);
    int r   = load_idx(etype, e, is64);
    atomicAdd(&g_rp2[dst * N_REL + r], 1);
}

// ---------------- 3-phase scan over 500k ----------------
__device__ __forceinline__ int block_exscan(int v) {
    int tid = threadIdx.x, lane = tid & 31, w = tid >> 5;
    __shared__ int wsum[8];
    int inc = v;
    #pragma unroll
    for (int o = 1; o < 32; o <<= 1) {
        int n = __shfl_up_sync(0xffffffffu, inc, o);
        if (lane >= o) inc += n;
    }
    if (lane == 31) wsum[w] = inc;
    __syncthreads();
    if (w == 0) {
        int s = (lane < 8) ? wsum[lane] : 0;
        #pragma unroll
        for (int o = 1; o < 8; o <<= 1) {
            int n = __shfl_up_sync(0xffffffffu, s, o);
            if (lane >= o) s += n;
        }
        if (lane < 8) wsum[lane] = s;
    }
    __syncthreads();
    int base = (w == 0) ? 0 : wsum[w - 1];
    return base + inc - v;
}
__global__ void scan1_kernel() {
    int i = blockIdx.x * 256 + threadIdx.x;
    int v = (i < NKEYS) ? g_rp2[i] : 0;
    int e = block_exscan(v);
    if (threadIdx.x == 255) g_bsum2[blockIdx.x] = e + v;
}
__global__ void scan2_kernel() {
    int t = threadIdx.x;
    int loc[8];
    int s = 0;
    #pragma unroll
    for (int j = 0; j < 8; j++) {
        int idx = t * 8 + j;
        int v = (idx < SCAN2B) ? g_bsum2[idx] : 0;
        loc[j] = s; s += v;
    }
    int base = block_exscan(s);
    #pragma unroll
    for (int j = 0; j < 8; j++) {
        int idx = t * 8 + j;
        if (idx < SCAN2B) g_boff2[idx] = base + loc[j];
    }
}
__global__ void scan3_kernel() {
    int i = blockIdx.x * 256 + threadIdx.x;
    int v = (i < NKEYS) ? g_rp2[i] : 0;
    int e = block_exscan(v);
    int off = g_boff2[blockIdx.x] + e;
    if (i < NKEYS) { g_rp2[i] = off; g_fill2[i] = off; }
    if (i == NKEYS - 1) g_rp2[NKEYS] = off + v;
}
__global__ void scatter_kernel(const void* ei, const void* etype) {
    int e = blockIdx.x * blockDim.x + threadIdx.x;
    if (e >= N_EDGES) return;
    int is64 = g_idx64;
    int src = load_idx(ei, e, is64);
    int dst = load_idx(ei, (long long)N_EDGES + e, is64);
    int r   = load_idx(etype, e, is64);
    int pos = atomicAdd(&g_fill2[dst * N_REL + r], 1);
    g_edge[pos] = src;
}

// ---------------- fused aggregate + GEMM(K=1408) + bias + LayerNorm ----------
// smem: Wsh[128][136]h (34816B) + Ash[128][136]h (34816B) + srp[1288]i (5152B)
// epilogue: Osh fp32 128x132 (67584B) aliases Wsh+Ash region (69632B)
#define MAIN_SMEM (34816 + 34816 + 5152)

extern "C" __global__ void __launch_bounds__(256, 2)
fused_kernel(const float* __restrict__ relB, const float* __restrict__ b_self,
             const float* __restrict__ gamma, const float* __restrict__ beta,
             float* __restrict__ out) {
    extern __shared__ __half smem[];
    __half* Wsh = smem;                     // [k][o], 128 x 136
    __half* Ash = smem + 128 * HSTRIDE;     // [m][k], 128 x 136
    int*    srp = (int*)(smem + 2 * 128 * HSTRIDE);   // byte 69632
    float*  Osh = (float*)smem;             // epilogue only (aliases W+A)

    int tid = threadIdx.x, wid = tid >> 5, lane = tid & 31;
    int d0 = blockIdx.x * 128;
    int count = min(128, N_NODES - d0);

    // rowptr2 slice for this block's 128 dst (1281 boundaries)
    int kb = d0 * N_REL;
    for (int i = tid; i < 1281; i += 256) {
        int idx = kb + i;
        if (idx > NKEYS) idx = NKEYS;
        srp[i] = g_rp2[idx];
    }
    __syncthreads();

    int g = lane >> 2, tg = lane & 3;
    int warp_m = wid & 3, warp_n = wid >> 2;         // 4 m x 2 n, warp tile 32x64
    int lt = lane >> 3, lr = lane & 7;
    uint32_t a_row_off = (uint32_t)((lt & 1) * 8 + lr) * HSTRIDE + (uint32_t)(lt >> 1) * 8;
    uint32_t b_base_off = ((uint32_t)((lt & 1) * 8 + lr)) * HSTRIDE
                        + (uint32_t)(warp_n * 64 + (lt >> 1) * 8);
    uint32_t sW = smem_u32(Wsh), sA = smem_u32(Ash);

    float acc[2][8][4];
    #pragma unroll
    for (int mt = 0; mt < 2; mt++)
        #pragma unroll
        for (int nt = 0; nt < 8; nt++)
            #pragma unroll
            for (int c = 0; c < 4; c++) acc[mt][nt][c] = 0.f;

    for (int r = 0; r <= N_REL; r++) {
        // async-load W_r while building A
        const __half* wsrc = g_wh + (size_t)r * DIM * DIM;
        #pragma unroll
        for (int it = 0; it < 8; it++) {
            int idx = it * 256 + tid;       // 0..2047
            int row = idx >> 4, q = idx & 15;
            CP_ASYNC16(sW + (uint32_t)(row * HSTRIDE + q * 8) * 2u,
                       wsrc + row * DIM + q * 8, 16);
        }
        CP_COMMIT();

        // build A tile: warp handles 16 dst rows; lane covers 4 k (8B)
        int dl = wid * 16;
        if (r < N_REL) {
            for (int i = 0; i < 16; i++) {
                int dd = dl + i;
                int s = srp[dd * N_REL + r], e = srp[dd * N_REL + r + 1];
                float sx = 0.f, sy = 0.f, sz = 0.f, sw = 0.f;
                for (int t = s; t < e; t++) {
                    int src = g_edge[t];
                    uint2 u = *(const uint2*)(g_xh + (size_t)src * DIM + lane * 4);
                    float2 lo = __half22float2(*(const __half2*)&u.x);
                    float2 hi = __half22float2(*(const __half2*)&u.y);
                    sx += lo.x; sy += lo.y; sz += hi.x; sw += hi.y;
                }
                __half2 h0 = __floats2half2_rn(sx, sy);
                __half2 h1 = __floats2half2_rn(sz, sw);
                uint2 st; st.x = *(uint32_t*)&h0; st.y = *(uint32_t*)&h1;
                *(uint2*)(Ash + dd * HSTRIDE + lane * 4) = st;
            }
        } else {
            // self "relation": A = x[dst]
            for (int i = 0; i < 16; i++) {
                int dd = dl + i;
                uint2 u = make_uint2(0u, 0u);
                if (dd < count)
                    u = *(const uint2*)(g_xh + (size_t)(d0 + dd) * DIM + lane * 4);
                *(uint2*)(Ash + dd * HSTRIDE + lane * 4) = u;
            }
        }
        CP_WAIT0();
        __syncthreads();

        // MMA: K=128 for this rel, accumulate into persistent acc
        uint32_t aAddr0 = sA + ((uint32_t)(warp_m * 32) * HSTRIDE + a_row_off) * 2u;
        uint32_t bAddr0 = sW + b_base_off * 2u;
        #pragma unroll
        for (int ks = 0; ks < 8; ks++) {
            uint32_t afr[2][4];
            ldm_x4(afr[0], aAddr0 + (uint32_t)(ks * 16) * 2u);
            ldm_x4(afr[1], aAddr0 + ((uint32_t)(16 * HSTRIDE + ks * 16)) * 2u);
            uint32_t bfr[4][4];
            #pragma unroll
            for (int p = 0; p < 4; p++)
                ldm_x4_t(bfr[p], bAddr0 + ((uint32_t)(ks * 16) * HSTRIDE
                                           + (uint32_t)(p * 16)) * 2u);
            #pragma unroll
            for (int mt = 0; mt < 2; mt++)
                #pragma unroll
                for (int p = 0; p < 4; p++) {
                    mma_f16(acc[mt][2 * p + 0], afr[mt], &bfr[p][0]);
                    mma_f16(acc[mt][2 * p + 1], afr[mt], &bfr[p][2]);
                }
        }
        __syncthreads();
    }

    // epilogue: acc -> Osh fp32 (aliases W/A smem; safe after last sync)
    #pragma unroll
    for (int mt = 0; mt < 2; mt++) {
        int r0 = warp_m * 32 + mt * 16 + g, r1 = r0 + 8;
        #pragma unroll
        for (int nt = 0; nt < 8; nt++) {
            int col = warp_n * 64 + nt * 8 + 2 * tg;
            *(float2*)&Osh[r0 * 132 + col] = make_float2(acc[mt][nt][0], acc[mt][nt][1]);
            *(float2*)&Osh[r1 * 132 + col] = make_float2(acc[mt][nt][2], acc[mt][nt][3]);
        }
    }
    __syncthreads();

    // per-row: + count*relB + b_self, LayerNorm, store
    for (int i = 0; i < 16; i++) {
        int lrow = wid * 16 + i;
        int n = d0 + lrow;
        if (lrow >= count) break;
        float4 v = *(float4*)&Osh[lrow * 132 + lane * 4];
        float4 bb = ((const float4*)b_self)[lane];
        #pragma unroll
        for (int r = 0; r < N_REL; r++) {
            int c = srp[lrow * N_REL + r + 1] - srp[lrow * N_REL + r];
            if (c) {
                float4 rb = ((const float4*)relB)[r * 32 + lane];
                float fc = (float)c;
                bb.x += fc * rb.x; bb.y += fc * rb.y;
                bb.z += fc * rb.z; bb.w += fc * rb.w;
            }
        }
        v.x += bb.x; v.y += bb.y; v.z += bb.z; v.w += bb.w;

        float sm = v.x + v.y + v.z + v.w;
        #pragma unroll
        for (int o = 16; o; o >>= 1) sm += __shfl_xor_sync(0xffffffffu, sm, o);
        float mean = sm * (1.0f / DIM);
        float dx = v.x - mean, dy = v.y - mean, dz = v.z - mean, dw = v.w - mean;
        float q = dx * dx + dy * dy + dz * dz + dw * dw;
        #pragma unroll
        for (int o = 16; o; o >>= 1) q += __shfl_xor_sync(0xffffffffu, q, o);
        float inv = rsqrtf(q * (1.0f / DIM) + LN_EPS);
        float4 gm = ((const float4*)gamma)[lane];
        float4 bt = ((const float4*)beta)[lane];
        float4 res;
        res.x = dx * inv * gm.x + bt.x;
        res.y = dy * inv * gm.y + bt.y;
        res.z = dz * inv * gm.z + bt.z;
        res.w = dw * inv * gm.w + bt.w;
        *((float4*)out + (size_t)n * 32 + lane) = res;
    }
}

// ---------------- launcher ----------------
extern "C" void kernel_launch(void* const* d_in, const int* in_sizes, int n_in,
                              void* d_out, int out_size) {
    const float* x      = (const float*)d_in[0];
    const void*  ei     = d_in[1];
    const void*  etype  = d_in[2];
    const float* relW   = (const float*)d_in[3];
    const float* relB   = (const float*)d_in[4];
    const float* w_self = (const float*)d_in[5];
    const float* b_self = (const float*)d_in[6];
    const float* gamma  = (const float*)d_in[7];
    const float* beta   = (const float*)d_in[8];
    float* out = (float*)d_out;

    cudaFuncSetAttribute(fused_kernel, cudaFuncAttributeMaxDynamicSharedMemorySize, MAIN_SMEM);

    int eg = (N_EDGES + 255) / 256;
    int zg = (NKEYS + 1 + 255) / 256;
    int prep_grid = (WH_ELEMS + XH_ELEMS + 255) / 256;

    detect_zero_kernel<<<zg, 256>>>((const unsigned int*)ei);       // 0
    prep_convert_kernel<<<prep_grid, 256>>>(relW, w_self, x);       // 1
    hist_kernel<<<eg, 256>>>(ei, etype);                            // 2
    scan1_kernel<<<SCAN2B, 256>>>();                                // 3
    scan2_kernel<<<1, 256>>>();                                     // 4
    scan3_kernel<<<SCAN2B, 256>>>();                                // 5
    scatter_kernel<<<eg, 256>>>(ei, etype);                         // 6
    fused_kernel<<<TILES, 256, MAIN_SMEM>>>(relB, b_self, gamma, beta, out);  // 7
}

// round 10
// speedup vs baseline: 1.5296x; 1.5296x over previous
#include <cuda_runtime.h>
#include <cuda_fp16.h>
#include <cstdint>

#define N_NODES 50000
#define N_EDGES 600000
#define DIM     128
#define N_REL   10
#define N_RELS  11      // 10 relations + self-loop as relation 10
#define LN_EPS  1e-5f
#define HSTRIDE 136     // padded smem row stride in halves (272 B)

#define TILES        391      // ceil(50000/128)
#define GROUPS       13
#define TILES_PER_G  31       // 13*31 = 403 >= 391
#define SCAN_B       196      // ceil(50000/256)
#define WH_ELEMS     (N_RELS * DIM * DIM)     // 180224
#define XH_ELEMS     (N_NODES * 16)           // uint4 chunks of x

// ---------------- device scratch (no allocations allowed) ----------------
__device__ int    g_idx64;
__device__ int    g_deg[N_NODES];
__device__ int    g_rowptr[N_NODES + 1];
__device__ int    g_fill[N_NODES];
__device__ int    g_bsum[256];
__device__ int    g_boff[256];
__device__ int    g_edge[N_EDGES];                      // (rel<<16)|src, bucketed by dst
__device__ __half g_wh[N_RELS * DIM * DIM];             // [rel][k][o] fp16
__device__ __half g_xh[(size_t)N_NODES * DIM];          // x fp16
__device__ __half g_xr[(size_t)N_RELS * N_NODES * DIM]; // [rel][node][out] (+bias), 140.8 MB

// ---------------- cp.async helpers ----------------
#define CP_ASYNC16(dst, src, sz) \
    asm volatile("cp.async.cg.shared.global [%0], [%1], 16, %2;" \
                 :: "r"(dst), "l"(src), "r"(sz))
#define CP_COMMIT() asm volatile("cp.async.commit_group;")
#define CP_WAIT1()  asm volatile("cp.async.wait_group 1;")
#define CP_WAIT0()  asm volatile("cp.async.wait_group 0;")

__device__ __forceinline__ uint32_t smem_u32(const void* p) {
    uint32_t a;
    asm("{ .reg .u64 t; cvta.to.shared.u64 t, %1; cvt.u32.u64 %0, t; }" : "=r"(a) : "l"(p));
    return a;
}
__device__ __forceinline__ void ldm_x4(uint32_t r[4], uint32_t addr) {
    asm volatile("ldmatrix.sync.aligned.m8n8.x4.shared.b16 {%0,%1,%2,%3}, [%4];"
        : "=r"(r[0]), "=r"(r[1]), "=r"(r[2]), "=r"(r[3]) : "r"(addr));
}
__device__ __forceinline__ void ldm_x4_t(uint32_t r[4], uint32_t addr) {
    asm volatile("ldmatrix.sync.aligned.m8n8.x4.trans.shared.b16 {%0,%1,%2,%3}, [%4];"
        : "=r"(r[0]), "=r"(r[1]), "=r"(r[2]), "=r"(r[3]) : "r"(addr));
}
__device__ __forceinline__ void mma_f16(float d[4], const uint32_t a[4],
                                        const uint32_t b[2]) {
    asm volatile(
        "mma.sync.aligned.m16n8k16.row.col.f32.f16.f16.f32 "
        "{%0,%1,%2,%3}, {%4,%5,%6,%7}, {%8,%9}, {%0,%1,%2,%3};\n"
        : "+f"(d[0]), "+f"(d[1]), "+f"(d[2]), "+f"(d[3])
        : "r"(a[0]), "r"(a[1]), "r"(a[2]), "r"(a[3]), "r"(b[0]), "r"(b[1]));
}

// ---------------- fused: zero g_deg + dtype detection ----------------
__global__ void detect_zero_kernel(const unsigned int* ew) {
    int i = blockIdx.x * blockDim.x + threadIdx.x;
    if (i < N_NODES) g_deg[i] = 0;
    if (blockIdx.x == 0) {
        __shared__ unsigned int any;
        if (threadIdx.x == 0) any = 0u;
        __syncthreads();
        unsigned int v = 0;
        #pragma unroll
        for (int t = 0; t < 4; t++) v |= ew[((threadIdx.x * 4 + t) << 1) + 1];
        if (v) atomicOr(&any, 1u);
        __syncthreads();
        if (threadIdx.x == 0) g_idx64 = (any == 0u) ? 1 : 0;
    }
}
__device__ __forceinline__ int load_idx(const void* p, long long i, int is64) {
    return is64 ? (int)((const long long*)p)[i] : ((const int*)p)[i];
}

// ---------------- fused fp16 prep: weights + x ----------------
__global__ void prep_convert_kernel(const float* __restrict__ relW,
                                    const float* __restrict__ w_self,
                                    const float* __restrict__ x) {
    int i = blockIdx.x * blockDim.x + threadIdx.x;
    if (i < WH_ELEMS) {
        int r = i >> 14;
        int j = i & 16383;                 // j = k*128 + o (target layout [k][o])
        float v;
        if (r < N_REL) v = relW[(size_t)r * DIM * DIM + j];            // relW native [k][o]
        else { int k = j >> 7, o = j & 127; v = w_self[o * DIM + k]; } // w_self [o][k]->[k][o]
        g_wh[i] = __float2half_rn(v);
    } else {
        int j = i - WH_ELEMS;
        if (j < XH_ELEMS) {
            const float4* src = (const float4*)x + j * 2;
            float4 a = src[0], b = src[1];
            __half2 h0 = __floats2half2_rn(a.x, a.y);
            __half2 h1 = __floats2half2_rn(a.z, a.w);
            __half2 h2 = __floats2half2_rn(b.x, b.y);
            __half2 h3 = __floats2half2_rn(b.z, b.w);
            uint4 pack;
            pack.x = *(uint32_t*)&h0; pack.y = *(uint32_t*)&h1;
            pack.z = *(uint32_t*)&h2; pack.w = *(uint32_t*)&h3;
            ((uint4*)g_xh)[j] = pack;
        }
    }
}

// ---------------- CSR-by-dst build ----------------
__global__ void hist_kernel(const void* ei) {
    int e = blockIdx.x * blockDim.x + threadIdx.x;
    if (e >= N_EDGES) return;
    int dst = load_idx(ei, (long long)N_EDGES + e, g_idx64);
    atomicAdd(&g_deg[dst], 1);
}
__device__ __forceinline__ int block_exscan(int v) {
    int tid = threadIdx.x, lane = tid & 31, w = tid >> 5;
    __shared__ int wsum[8];
    int inc = v;
    #pragma unroll
    for (int o = 1; o < 32; o <<= 1) {
        int n = __shfl_up_sync(0xffffffffu, inc, o);
        if (lane >= o) inc += n;
    }
    if (lane == 31) wsum[w] = inc;
    __syncthreads();
    if (w == 0) {
        int s = (lane < 8) ? wsum[lane] : 0;
        #pragma unroll
        for (int o = 1; o < 8; o <<= 1) {
            int n = __shfl_up_sync(0xffffffffu, s, o);
            if (lane >= o) s += n;
        }
        if (lane < 8) wsum[lane] = s;
    }
    __syncthreads();
    int base = (w == 0) ? 0 : wsum[w - 1];
    return base + inc - v;
}
__global__ void scan1_kernel() {
    int i = blockIdx.x * 256 + threadIdx.x;
    int v = (i < N_NODES) ? g_deg[i] : 0;
    int e = block_exscan(v);
    if (threadIdx.x == 255) g_bsum[blockIdx.x] = e + v;
}
__global__ void scan2_kernel() {
    int t = threadIdx.x;
    int v = (t < SCAN_B) ? g_bsum[t] : 0;
    int e = block_exscan(v);
    if (t < SCAN_B) g_boff[t] = e;
}
__global__ void scan3_kernel() {
    int i = blockIdx.x * 256 + threadIdx.x;
    int v = (i < N_NODES) ? g_deg[i] : 0;
    int e = block_exscan(v);
    int off = g_boff[blockIdx.x] + e;
    if (i < N_NODES) { g_rowptr[i] = off; g_fill[i] = off; }
    if (i == N_NODES - 1) g_rowptr[N_NODES] = off + v;
}
__global__ void scatter_kernel(const void* ei, const void* etype) {
    int e = blockIdx.x * blockDim.x + threadIdx.x;
    if (e >= N_EDGES) return;
    int is64 = g_idx64;
    int src = load_idx(ei, e, is64);
    int dst = load_idx(ei, (long long)N_EDGES + e, is64);
    int r   = load_idx(etype, e, is64);
    int pos = atomicAdd(&g_fill[dst], 1);
    g_edge[pos] = (r << 16) | src;             // src < 50000 < 2^16
}

// ---------------- fp16 tensor-core GEMM, warp tile 32x64, staged epilogue ----
// smem (halves): Bsh[128][136] + A0[128][136] + A1[128][136] + Osh[128][136] + bias
#define TILE_HALVES (128 * HSTRIDE)
#define GEMM_SMEM   (4 * TILE_HALVES * 2 + 512)

__device__ __forceinline__ void prefetch_tile(uint32_t sA, int base, int tid) {
    #pragma unroll
    for (int it = 0; it < 8; it++) {
        int idx = it * 256 + tid;               // 0..2047
        int row = idx >> 4, q = idx & 15;       // q: 16B chunk (8 halves)
        int node = base + row;
        const __half* src = g_xh + (size_t)node * DIM + q * 8;
        uint32_t dst = sA + (uint32_t)(row * HSTRIDE + q * 8) * 2u;
        int sz = (node < N_NODES) ? 16 : 0;
        CP_ASYNC16(dst, src, sz);
    }
    CP_COMMIT();
}

extern "C" __global__ void __launch_bounds__(256, 1)
gemm_kernel(const float* __restrict__ relB, const float* __restrict__ b_self) {
    extern __shared__ __half smem[];
    __half* Bsh = smem;                  // [k][o] layout, 128 k-rows x 136
    __half* A0  = smem + TILE_HALVES;    // [m][k]
    __half* A1  = A0 + TILE_HALVES;
    __half* Osh = A1 + TILE_HALVES;      // epilogue staging, 128 x 136
    float* bias_sh = (float*)(Osh + TILE_HALVES);   // 128 floats

    int tid = threadIdx.x, wid = tid >> 5, lane = tid & 31;
    int rel = blockIdx.y;
    int t0 = blockIdx.x * TILES_PER_G;
    int t1 = min(t0 + TILES_PER_G, TILES);
    if (t0 >= TILES) return;

    // load this relation's weights [k][o] fp16 straight into smem
    const uint4* bg = (const uint4*)(g_wh + (size_t)rel * DIM * DIM);
    for (int idx = tid; idx < 128 * 16; idx += 256) {
        int row = idx >> 4, q = idx & 15;
        *(uint4*)&Bsh[row * HSTRIDE + q * 8] = bg[idx];
    }
    if (tid < 128) {
        const float* bias = (rel < N_REL) ? (relB + rel * DIM) : b_self;
        bias_sh[tid] = bias[tid];
    }

    int g = lane >> 2, tg = lane & 3;
    int warp_m = wid & 3, warp_n = wid >> 2;   // 4 m-warps x 2 n-warps (32x64 tile)

    // per-lane ldmatrix address pieces
    int lt = lane >> 3, lr = lane & 7;
    uint32_t a_row_off = (uint32_t)((lt & 1) * 8 + lr) * HSTRIDE + (uint32_t)(lt >> 1) * 8;
    uint32_t b_base_off = ((uint32_t)((lt & 1) * 8 + lr)) * HSTRIDE
                        + (uint32_t)(warp_n * 64 + (lt >> 1) * 8);
    uint32_t sB = smem_u32(Bsh);
    uint32_t sA0 = smem_u32(A0), sA1 = smem_u32(A1);

    prefetch_tile(sA0, t0 * 128, tid);

    for (int t = t0; t < t1; t++) {
        int li = t - t0;
        uint32_t sAc = (li & 1) ? sA1 : sA0;
        if (t + 1 < t1) {
            prefetch_tile((li & 1) ? sA0 : sA1, (t + 1) * 128, tid);
            CP_WAIT1();
        } else {
            CP_WAIT0();
        }
        __syncthreads();

        float acc[2][8][4];
        #pragma unroll
        for (int mt = 0; mt < 2; mt++)
            #pragma unroll
            for (int nt = 0; nt < 8; nt++)
                #pragma unroll
                for (int c = 0; c < 4; c++) acc[mt][nt][c] = 0.f;

        uint32_t aAddr0 = sAc + ((uint32_t)(warp_m * 32) * HSTRIDE + a_row_off) * 2u;
        uint32_t bAddr0 = sB + b_base_off * 2u;

        #pragma unroll
        for (int ks = 0; ks < 8; ks++) {       // k0 = ks*16
            uint32_t afr[2][4];
            ldm_x4(afr[0], aAddr0 + (uint32_t)(ks * 16) * 2u);
            ldm_x4(afr[1], aAddr0 + ((uint32_t)(16 * HSTRIDE + ks * 16)) * 2u);
            uint32_t bfr[4][4];                // pairs: nt = 2*p, 2*p+1
            #pragma unroll
            for (int p = 0; p < 4; p++)
                ldm_x4_t(bfr[p], bAddr0 + ((uint32_t)(ks * 16) * HSTRIDE
                                           + (uint32_t)(p * 16)) * 2u);
            #pragma unroll
            for (int mt = 0; mt < 2; mt++)
                #pragma unroll
                for (int p = 0; p < 4; p++) {
                    mma_f16(acc[mt][2 * p + 0], afr[mt], &bfr[p][0]);
                    mma_f16(acc[mt][2 * p + 1], afr[mt], &bfr[p][2]);
                }
        }

        // epilogue stage 1: + bias, fp16, into Osh (conflict-free STS.32)
        #pragma unroll
        for (int mt = 0; mt < 2; mt++) {
            int r0 = warp_m * 32 + mt * 16 + g;
            int r1 = r0 + 8;
            #pragma unroll
            for (int nt = 0; nt < 8; nt++) {
                int col = warp_n * 64 + nt * 8 + 2 * tg;
                float bx = bias_sh[col], by = bias_sh[col + 1];
                *(__half2*)(Osh + r0 * HSTRIDE + col) =
                    __floats2half2_rn(acc[mt][nt][0] + bx, acc[mt][nt][1] + by);
                *(__half2*)(Osh + r1 * HSTRIDE + col) =
                    __floats2half2_rn(acc[mt][nt][2] + bx, acc[mt][nt][3] + by);
            }
        }
        __syncthreads();

        // epilogue stage 2: coalesced uint4 stores to g_xr
        int base = t * 128;
        int count = min(128, N_NODES - base);
        __half* dbase = g_xr + ((size_t)rel * N_NODES + base) * DIM;
        #pragma unroll
        for (int it = 0; it < 8; it++) {
            int idx = it * 256 + tid;           // 0..2047
            int row = idx >> 4, q = idx & 15;
            if (row < count) {
                uint4 v = *(const uint4*)(Osh + row * HSTRIDE + q * 8);
                *(uint4*)(dbase + (size_t)row * DIM + q * 8) = v;
            }
        }
        __syncthreads();   // A buffer + Osh reuse guard
    }
}

// ---------------- fused gather + segment-sum + LayerNorm ----------------
extern "C" __global__ void __launch_bounds__(256)
final_kernel(const float* __restrict__ gamma, const float* __restrict__ beta,
             float* __restrict__ out) {
    int gw = (blockIdx.x * blockDim.x + threadIdx.x) >> 5;
    if (gw >= N_NODES) return;
    int lane = threadIdx.x & 31;

    float ax, ay, az, aw;
    {
        uint2 u = *(const uint2*)(g_xr + ((size_t)N_REL * N_NODES + gw) * DIM + lane * 4);
        float2 lo = __half22float2(*(const __half2*)&u.x);
        float2 hi = __half22float2(*(const __half2*)&u.y);
        ax = lo.x; ay = lo.y; az = hi.x; aw = hi.y;
    }

    int s = g_rowptr[gw], e = g_rowptr[gw + 1];
    int t = s;
    for (; t + 3 < e; t += 4) {
        int p0 = g_edge[t], p1 = g_edge[t + 1], p2 = g_edge[t + 2], p3 = g_edge[t + 3];
        uint2 u0 = *(const uint2*)(g_xr + ((size_t)(p0 >> 16) * N_NODES + (p0 & 0xFFFF)) * DIM + lane * 4);
        uint2 u1 = *(const uint2*)(g_xr + ((size_t)(p1 >> 16) * N_NODES + (p1 & 0xFFFF)) * DIM + lane * 4);
        uint2 u2 = *(const uint2*)(g_xr + ((size_t)(p2 >> 16) * N_NODES + (p2 & 0xFFFF)) * DIM + lane * 4);
        uint2 u3 = *(const uint2*)(g_xr + ((size_t)(p3 >> 16) * N_NODES + (p3 & 0xFFFF)) * DIM + lane * 4);
        float2 a0 = __half22float2(*(const __half2*)&u0.x), b0 = __half22float2(*(const __half2*)&u0.y);
        float2 a1 = __half22float2(*(const __half2*)&u1.x), b1 = __half22float2(*(const __half2*)&u1.y);
        float2 a2 = __half22float2(*(const __half2*)&u2.x), b2 = __half22float2(*(const __half2*)&u2.y);
        float2 a3 = __half22float2(*(const __half2*)&u3.x), b3 = __half22float2(*(const __half2*)&u3.y);
        ax += (a0.x + a1.x) + (a2.x + a3.x);
        ay += (a0.y + a1.y) + (a2.y + a3.y);
        az += (b0.x + b1.x) + (b2.x + b3.x);
        aw += (b0.y + b1.y) + (b2.y + b3.y);
    }
    for (; t < e; t++) {
        int p = g_edge[t];
        uint2 u = *(const uint2*)(g_xr + ((size_t)(p >> 16) * N_NODES + (p & 0xFFFF)) * DIM + lane * 4);
        float2 lo = __half22float2(*(const __half2*)&u.x);
        float2 hi = __half22float2(*(const __half2*)&u.y);
        ax += lo.x; ay += lo.y; az += hi.x; aw += hi.y;
    }

    float sm = ax + ay + az + aw;
    #pragma unroll
    for (int o = 16; o; o >>= 1) sm += __shfl_xor_sync(0xffffffffu, sm, o);
    float mean = sm * (1.0f / DIM);
    float dx = ax - mean, dy = ay - mean, dz = az - mean, dw = aw - mean;
    float q = dx * dx + dy * dy + dz * dz + dw * dw;
    #pragma unroll
    for (int o = 16; o; o >>= 1) q += __shfl_xor_sync(0xffffffffu, q, o);
    float inv = rsqrtf(q * (1.0f / DIM) + LN_EPS);
    float4 gm = ((const float4*)gamma)[lane];
    float4 bt = ((const float4*)beta)[lane];
    float4 v;
    v.x = dx * inv * gm.x + bt.x;
    v.y = dy * inv * gm.y + bt.y;
    v.z = dz * inv * gm.z + bt.z;
    v.w = dw * inv * gm.w + bt.w;
    *((float4*)out + (size_t)gw * 32 + lane) = v;
}

// ---------------- launcher ----------------
extern "C" void kernel_launch(void* const* d_in, const int* in_sizes, int n_in,
                              void* d_out, int out_size) {
    const float* x      = (const float*)d_in[0];
    const void*  ei     = d_in[1];
    const void*  etype  = d_in[2];
    const float* relW   = (const float*)d_in[3];
    const float* relB   = (const float*)d_in[4];
    const float* w_self = (const float*)d_in[5];
    const float* b_self = (const float*)d_in[6];
    const float* gamma  = (const float*)d_in[7];
    const float* beta   = (const float*)d_in[8];
    float* out = (float*)d_out;

    cudaFuncSetAttribute(gemm_kernel, cudaFuncAttributeMaxDynamicSharedMemorySize, GEMM_SMEM);

    int eg = (N_EDGES + 255) / 256;
    int prep_grid = (WH_ELEMS + XH_ELEMS + 255) / 256;

    // gemm kept at launch index 3 (observed ncu profiling slot)
    detect_zero_kernel<<<(N_NODES + 255) / 256, 256>>>((const unsigned int*)ei); // 0
    prep_convert_kernel<<<prep_grid, 256>>>(relW, w_self, x);                    // 1
    hist_kernel<<<eg, 256>>>(ei);                                                // 2
    dim3 ggrid(GROUPS, N_RELS);
    gemm_kernel<<<ggrid, 256, GEMM_SMEM>>>(relB, b_self);                        // 3

    scan1_kernel<<<SCAN_B, 256>>>();
    scan2_kernel<<<1, 256>>>();
    scan3_kernel<<<SCAN_B, 256>>>();
    scatter_kernel<<<eg, 256>>>(ei, etype);

    final_kernel<<<(N_NODES * 32 + 255) / 256, 256>>>(gamma, beta, out);
}

// round 11
// speedup vs baseline: 1.7204x; 1.1247x over previous
#include <cuda_runtime.h>
#include <cuda_fp16.h>
#include <cstdint>

#define N_NODES 50000
#define N_EDGES 600000
#define DIM     128
#define N_REL   10
#define N_RELS  11      // 10 relations + self-loop as relation 10
#define LN_EPS  1e-5f
#define HSTRIDE 136     // padded smem row stride in halves (272 B)

#define TILES        391      // ceil(50000/128)
#define GROUPS       13
#define TILES_PER_G  31       // 13*31 = 403 >= 391
#define SCAN_B       196      // ceil(50000/256)
#define WH_ELEMS     (N_RELS * DIM * DIM)     // 180224
#define XH_ELEMS     (N_NODES * 16)           // uint4 chunks of x

// ---------------- device scratch (no allocations allowed) ----------------
__device__ int    g_idx64;
__device__ int    g_deg[N_NODES];
__device__ int    g_rowptr[N_NODES + 1];
__device__ int    g_fill[N_NODES];
__device__ int    g_bsum[256];
__device__ int    g_boff[256];
__device__ int    g_edge[N_EDGES];                      // (rel<<16)|src, bucketed by dst
__device__ __half g_wh[N_RELS * DIM * DIM];             // [rel][k][o] fp16
__device__ __half g_xh[(size_t)N_NODES * DIM];          // x fp16
__device__ __half g_xr[(size_t)N_RELS * N_NODES * DIM]; // [rel][node][out] (+bias), 140.8 MB

// ---------------- cp.async helpers ----------------
#define CP_ASYNC16(dst, src, sz) \
    asm volatile("cp.async.cg.shared.global [%0], [%1], 16, %2;" \
                 :: "r"(dst), "l"(src), "r"(sz))
#define CP_COMMIT() asm volatile("cp.async.commit_group;")
#define CP_WAIT1()  asm volatile("cp.async.wait_group 1;")
#define CP_WAIT0()  asm volatile("cp.async.wait_group 0;")

__device__ __forceinline__ uint32_t smem_u32(const void* p) {
    uint32_t a;
    asm("{ .reg .u64 t; cvta.to.shared.u64 t, %1; cvt.u32.u64 %0, t; }" : "=r"(a) : "l"(p));
    return a;
}
__device__ __forceinline__ void ldm_x4(uint32_t r[4], uint32_t addr) {
    asm volatile("ldmatrix.sync.aligned.m8n8.x4.shared.b16 {%0,%1,%2,%3}, [%4];"
        : "=r"(r[0]), "=r"(r[1]), "=r"(r[2]), "=r"(r[3]) : "r"(addr));
}
__device__ __forceinline__ void ldm_x4_t(uint32_t r[4], uint32_t addr) {
    asm volatile("ldmatrix.sync.aligned.m8n8.x4.trans.shared.b16 {%0,%1,%2,%3}, [%4];"
        : "=r"(r[0]), "=r"(r[1]), "=r"(r[2]), "=r"(r[3]) : "r"(addr));
}
__device__ __forceinline__ void mma_f16(float d[4], const uint32_t a[4],
                                        const uint32_t b[2]) {
    asm volatile(
        "mma.sync.aligned.m16n8k16.row.col.f32.f16.f16.f32 "
        "{%0,%1,%2,%3}, {%4,%5,%6,%7}, {%8,%9}, {%0,%1,%2,%3};\n"
        : "+f"(d[0]), "+f"(d[1]), "+f"(d[2]), "+f"(d[3])
        : "r"(a[0]), "r"(a[1]), "r"(a[2]), "r"(a[3]), "r"(b[0]), "r"(b[1]));
}

// ---------------- fused: zero g_deg + dtype detection ----------------
__global__ void detect_zero_kernel(const unsigned int* ew) {
    int i = blockIdx.x * blockDim.x + threadIdx.x;
    if (i < N_NODES) g_deg[i] = 0;
    if (blockIdx.x == 0) {
        __shared__ unsigned int any;
        if (threadIdx.x == 0) any = 0u;
        __syncthreads();
        unsigned int v = 0;
        #pragma unroll
        for (int t = 0; t < 4; t++) v |= ew[((threadIdx.x * 4 + t) << 1) + 1];
        if (v) atomicOr(&any, 1u);
        __syncthreads();
        if (threadIdx.x == 0) g_idx64 = (any == 0u) ? 1 : 0;
    }
}
__device__ __forceinline__ int load_idx(const void* p, long long i, int is64) {
    return is64 ? (int)((const long long*)p)[i] : ((const int*)p)[i];
}

// ---------------- fused fp16 prep: weights + x ----------------
__global__ void prep_convert_kernel(const float* __restrict__ relW,
                                    const float* __restrict__ w_self,
                                    const float* __restrict__ x) {
    int i = blockIdx.x * blockDim.x + threadIdx.x;
    if (i < WH_ELEMS) {
        int r = i >> 14;
        int j = i & 16383;                 // j = k*128 + o (target layout [k][o])
        float v;
        if (r < N_REL) v = relW[(size_t)r * DIM * DIM + j];            // relW native [k][o]
        else { int k = j >> 7, o = j & 127; v = w_self[o * DIM + k]; } // w_self [o][k]->[k][o]
        g_wh[i] = __float2half_rn(v);
    } else {
        int j = i - WH_ELEMS;
        if (j < XH_ELEMS) {
            const float4* src = (const float4*)x + j * 2;
            float4 a = src[0], b = src[1];
            __half2 h0 = __floats2half2_rn(a.x, a.y);
            __half2 h1 = __floats2half2_rn(a.z, a.w);
            __half2 h2 = __floats2half2_rn(b.x, b.y);
            __half2 h3 = __floats2half2_rn(b.z, b.w);
            uint4 pack;
            pack.x = *(uint32_t*)&h0; pack.y = *(uint32_t*)&h1;
            pack.z = *(uint32_t*)&h2; pack.w = *(uint32_t*)&h3;
            ((uint4*)g_xh)[j] = pack;
        }
    }
}

// ---------------- CSR-by-dst build ----------------
__global__ void hist_kernel(const void* ei) {
    int e = blockIdx.x * blockDim.x + threadIdx.x;
    if (e >= N_EDGES) return;
    int dst = load_idx(ei, (long long)N_EDGES + e, g_idx64);
    atomicAdd(&g_deg[dst], 1);
}
__device__ __forceinline__ int block_exscan(int v) {
    int tid = threadIdx.x, lane = tid & 31, w = tid >> 5;
    __shared__ int wsum[8];
    int inc = v;
    #pragma unroll
    for (int o = 1; o < 32; o <<= 1) {
        int n = __shfl_up_sync(0xffffffffu, inc, o);
        if (lane >= o) inc += n;
    }
    if (lane == 31) wsum[w] = inc;
    __syncthreads();
    if (w == 0) {
        int s = (lane < 8) ? wsum[lane] : 0;
        #pragma unroll
        for (int o = 1; o < 8; o <<= 1) {
            int n = __shfl_up_sync(0xffffffffu, s, o);
            if (lane >= o) s += n;
        }
        if (lane < 8) wsum[lane] = s;
    }
    __syncthreads();
    int base = (w == 0) ? 0 : wsum[w - 1];
    return base + inc - v;
}
__global__ void scan1_kernel() {
    int i = blockIdx.x * 256 + threadIdx.x;
    int v = (i < N_NODES) ? g_deg[i] : 0;
    int e = block_exscan(v);
    if (threadIdx.x == 255) g_bsum[blockIdx.x] = e + v;
}
__global__ void scan2_kernel() {
    int t = threadIdx.x;
    int v = (t < SCAN_B) ? g_bsum[t] : 0;
    int e = block_exscan(v);
    if (t < SCAN_B) g_boff[t] = e;
}
__global__ void scan3_kernel() {
    int i = blockIdx.x * 256 + threadIdx.x;
    int v = (i < N_NODES) ? g_deg[i] : 0;
    int e = block_exscan(v);
    int off = g_boff[blockIdx.x] + e;
    if (i < N_NODES) { g_rowptr[i] = off; g_fill[i] = off; }
    if (i == N_NODES - 1) g_rowptr[N_NODES] = off + v;
}
__global__ void scatter_kernel(const void* ei, const void* etype) {
    int e = blockIdx.x * blockDim.x + threadIdx.x;
    if (e >= N_EDGES) return;
    int is64 = g_idx64;
    int src = load_idx(ei, e, is64);
    int dst = load_idx(ei, (long long)N_EDGES + e, is64);
    int r   = load_idx(etype, e, is64);
    int pos = atomicAdd(&g_fill[dst], 1);
    g_edge[pos] = (r << 16) | src;             // src < 50000 < 2^16
}

// ---------------- fp16 tensor-core GEMM, warp tile 32x64, staged epilogue ----
// smem (halves): Bsh[128][136] + A0[128][136] + A1[128][136] + Osh[128][136] + bias
#define TILE_HALVES (128 * HSTRIDE)
#define GEMM_SMEM   (4 * TILE_HALVES * 2 + 512)

__device__ __forceinline__ void prefetch_tile(uint32_t sA, int base, int tid) {
    #pragma unroll
    for (int it = 0; it < 8; it++) {
        int idx = it * 256 + tid;               // 0..2047
        int row = idx >> 4, q = idx & 15;       // q: 16B chunk (8 halves)
        int node = base + row;
        const __half* src = g_xh + (size_t)node * DIM + q * 8;
        uint32_t dst = sA + (uint32_t)(row * HSTRIDE + q * 8) * 2u;
        int sz = (node < N_NODES) ? 16 : 0;
        CP_ASYNC16(dst, src, sz);
    }
    CP_COMMIT();
}

extern "C" __global__ void __launch_bounds__(256, 1)
gemm_kernel(const float* __restrict__ relB, const float* __restrict__ b_self) {
    extern __shared__ __half smem[];
    __half* Bsh = smem;                  // [k][o] layout, 128 k-rows x 136
    __half* A0  = smem + TILE_HALVES;    // [m][k]
    __half* A1  = A0 + TILE_HALVES;
    __half* Osh = A1 + TILE_HALVES;      // epilogue staging, 128 x 136
    float* bias_sh = (float*)(Osh + TILE_HALVES);   // 128 floats

    int tid = threadIdx.x, wid = tid >> 5, lane = tid & 31;
    int rel = blockIdx.y;
    int t0 = blockIdx.x * TILES_PER_G;
    int t1 = min(t0 + TILES_PER_G, TILES);
    if (t0 >= TILES) return;

    // load this relation's weights [k][o] fp16 straight into smem
    const uint4* bg = (const uint4*)(g_wh + (size_t)rel * DIM * DIM);
    for (int idx = tid; idx < 128 * 16; idx += 256) {
        int row = idx >> 4, q = idx & 15;
        *(uint4*)&Bsh[row * HSTRIDE + q * 8] = bg[idx];
    }
    if (tid < 128) {
        const float* bias = (rel < N_REL) ? (relB + rel * DIM) : b_self;
        bias_sh[tid] = bias[tid];
    }

    int g = lane >> 2, tg = lane & 3;
    int warp_m = wid & 3, warp_n = wid >> 2;   // 4 m-warps x 2 n-warps (32x64 tile)

    // per-lane ldmatrix address pieces
    int lt = lane >> 3, lr = lane & 7;
    uint32_t a_row_off = (uint32_t)((lt & 1) * 8 + lr) * HSTRIDE + (uint32_t)(lt >> 1) * 8;
    uint32_t b_base_off = ((uint32_t)((lt & 1) * 8 + lr)) * HSTRIDE
                        + (uint32_t)(warp_n * 64 + (lt >> 1) * 8);
    uint32_t sB = smem_u32(Bsh);
    uint32_t sA0 = smem_u32(A0), sA1 = smem_u32(A1);

    prefetch_tile(sA0, t0 * 128, tid);

    for (int t = t0; t < t1; t++) {
        int li = t - t0;
        uint32_t sAc = (li & 1) ? sA1 : sA0;
        if (t + 1 < t1) {
            prefetch_tile((li & 1) ? sA0 : sA1, (t + 1) * 128, tid);
            CP_WAIT1();
        } else {
            CP_WAIT0();
        }
        __syncthreads();

        float acc[2][8][4];
        #pragma unroll
        for (int mt = 0; mt < 2; mt++)
            #pragma unroll
            for (int nt = 0; nt < 8; nt++)
                #pragma unroll
                for (int c = 0; c < 4; c++) acc[mt][nt][c] = 0.f;

        uint32_t aAddr0 = sAc + ((uint32_t)(warp_m * 32) * HSTRIDE + a_row_off) * 2u;
        uint32_t bAddr0 = sB + b_base_off * 2u;

        #pragma unroll
        for (int ks = 0; ks < 8; ks++) {       // k0 = ks*16
            uint32_t afr[2][4];
            ldm_x4(afr[0], aAddr0 + (uint32_t)(ks * 16) * 2u);
            ldm_x4(afr[1], aAddr0 + ((uint32_t)(16 * HSTRIDE + ks * 16)) * 2u);
            uint32_t bfr[4][4];                // pairs: nt = 2*p, 2*p+1
            #pragma unroll
            for (int p = 0; p < 4; p++)
                ldm_x4_t(bfr[p], bAddr0 + ((uint32_t)(ks * 16) * HSTRIDE
                                           + (uint32_t)(p * 16)) * 2u);
            #pragma unroll
            for (int mt = 0; mt < 2; mt++)
                #pragma unroll
                for (int p = 0; p < 4; p++) {
                    mma_f16(acc[mt][2 * p + 0], afr[mt], &bfr[p][0]);
                    mma_f16(acc[mt][2 * p + 1], afr[mt], &bfr[p][2]);
                }
        }

        // epilogue stage 1: + bias, fp16, into Osh (conflict-free STS.32)
        #pragma unroll
        for (int mt = 0; mt < 2; mt++) {
            int r0 = warp_m * 32 + mt * 16 + g;
            int r1 = r0 + 8;
            #pragma unroll
            for (int nt = 0; nt < 8; nt++) {
                int col = warp_n * 64 + nt * 8 + 2 * tg;
                float bx = bias_sh[col], by = bias_sh[col + 1];
                *(__half2*)(Osh + r0 * HSTRIDE + col) =
                    __floats2half2_rn(acc[mt][nt][0] + bx, acc[mt][nt][1] + by);
                *(__half2*)(Osh + r1 * HSTRIDE + col) =
                    __floats2half2_rn(acc[mt][nt][2] + bx, acc[mt][nt][3] + by);
            }
        }
        __syncthreads();

        // epilogue stage 2: coalesced uint4 stores to g_xr
        int base = t * 128;
        int count = min(128, N_NODES - base);
        __half* dbase = g_xr + ((size_t)rel * N_NODES + base) * DIM;
        #pragma unroll
        for (int it = 0; it < 8; it++) {
            int idx = it * 256 + tid;           // 0..2047
            int row = idx >> 4, q = idx & 15;
            if (row < count) {
                uint4 v = *(const uint4*)(Osh + row * HSTRIDE + q * 8);
                *(uint4*)(dbase + (size_t)row * DIM + q * 8) = v;
            }
        }
        __syncthreads();   // A buffer + Osh reuse guard
    }
}

// ---------------- fused gather + segment-sum + LayerNorm ----------------
extern "C" __global__ void __launch_bounds__(256)
final_kernel(const float* __restrict__ gamma, const float* __restrict__ beta,
             float* __restrict__ out) {
    int gw = (blockIdx.x * blockDim.x + threadIdx.x) >> 5;
    if (gw >= N_NODES) return;
    int lane = threadIdx.x & 31;

    float ax, ay, az, aw;
    {
        uint2 u = *(const uint2*)(g_xr + ((size_t)N_REL * N_NODES + gw) * DIM + lane * 4);
        float2 lo = __half22float2(*(const __half2*)&u.x);
        float2 hi = __half22float2(*(const __half2*)&u.y);
        ax = lo.x; ay = lo.y; az = hi.x; aw = hi.y;
    }

    int s = g_rowptr[gw], e = g_rowptr[gw + 1];
    int t = s;
    for (; t + 3 < e; t += 4) {
        int p0 = g_edge[t], p1 = g_edge[t + 1], p2 = g_edge[t + 2], p3 = g_edge[t + 3];
        uint2 u0 = *(const uint2*)(g_xr + ((size_t)(p0 >> 16) * N_NODES + (p0 & 0xFFFF)) * DIM + lane * 4);
        uint2 u1 = *(const uint2*)(g_xr + ((size_t)(p1 >> 16) * N_NODES + (p1 & 0xFFFF)) * DIM + lane * 4);
        uint2 u2 = *(const uint2*)(g_xr + ((size_t)(p2 >> 16) * N_NODES + (p2 & 0xFFFF)) * DIM + lane * 4);
        uint2 u3 = *(const uint2*)(g_xr + ((size_t)(p3 >> 16) * N_NODES + (p3 & 0xFFFF)) * DIM + lane * 4);
        float2 a0 = __half22float2(*(const __half2*)&u0.x), b0 = __half22float2(*(const __half2*)&u0.y);
        float2 a1 = __half22float2(*(const __half2*)&u1.x), b1 = __half22float2(*(const __half2*)&u1.y);
        float2 a2 = __half22float2(*(const __half2*)&u2.x), b2 = __half22float2(*(const __half2*)&u2.y);
        float2 a3 = __half22float2(*(const __half2*)&u3.x), b3 = __half22float2(*(const __half2*)&u3.y);
        ax += (a0.x + a1.x) + (a2.x + a3.x);
        ay += (a0.y + a1.y) + (a2.y + a3.y);
        az += (b0.x + b1.x) + (b2.x + b3.x);
        aw += (b0.y + b1.y) + (b2.y + b3.y);
    }
    for (; t < e; t++) {
        int p = g_edge[t];
        uint2 u = *(const uint2*)(g_xr + ((size_t)(p >> 16) * N_NODES + (p & 0xFFFF)) * DIM + lane * 4);
        float2 lo = __half22float2(*(const __half2*)&u.x);
        float2 hi = __half22float2(*(const __half2*)&u.y);
        ax += lo.x; ay += lo.y; az += hi.x; aw += hi.y;
    }

    float sm = ax + ay + az + aw;
    #pragma unroll
    for (int o = 16; o; o >>= 1) sm += __shfl_xor_sync(0xffffffffu, sm, o);
    float mean = sm * (1.0f / DIM);
    float dx = ax - mean, dy = ay - mean, dz = az - mean, dw = aw - mean;
    float q = dx * dx + dy * dy + dz * dz + dw * dw;
    #pragma unroll
    for (int o = 16; o; o >>= 1) q += __shfl_xor_sync(0xffffffffu, q, o);
    float inv = rsqrtf(q * (1.0f / DIM) + LN_EPS);
    float4 gm = ((const float4*)gamma)[lane];
    float4 bt = ((const float4*)beta)[lane];
    float4 v;
    v.x = dx * inv * gm.x + bt.x;
    v.y = dy * inv * gm.y + bt.y;
    v.z = dz * inv * gm.z + bt.z;
    v.w = dw * inv * gm.w + bt.w;
    *((float4*)out + (size_t)gw * 32 + lane) = v;
}

// ---------------- launcher: fork CSR build parallel to GEMM ----------------
extern "C" void kernel_launch(void* const* d_in, const int* in_sizes, int n_in,
                              void* d_out, int out_size) {
    const float* x      = (const float*)d_in[0];
    const void*  ei     = d_in[1];
    const void*  etype  = d_in[2];
    const float* relW   = (const float*)d_in[3];
    const float* relB   = (const float*)d_in[4];
    const float* w_self = (const float*)d_in[5];
    const float* b_self = (const float*)d_in[6];
    const float* gamma  = (const float*)d_in[7];
    const float* beta   = (const float*)d_in[8];
    float* out = (float*)d_out;

    cudaFuncSetAttribute(gemm_kernel, cudaFuncAttributeMaxDynamicSharedMemorySize, GEMM_SMEM);

    int eg = (N_EDGES + 255) / 256;
    int prep_grid = (WH_ELEMS + XH_ELEMS + 255) / 256;

    // side stream + events for graph fork/join (host objects only, no device mem)
    cudaStream_t s1;
    cudaStreamCreateWithFlags(&s1, cudaStreamNonBlocking);
    cudaEvent_t evFork, evJoin;
    cudaEventCreateWithFlags(&evFork, cudaEventDisableTiming);
    cudaEventCreateWithFlags(&evJoin, cudaEventDisableTiming);

    // root: dtype detect + zero deg (both branches depend on it)
    detect_zero_kernel<<<(N_NODES + 255) / 256, 256>>>((const unsigned int*)ei);
    cudaEventRecord(evFork, 0);
    cudaStreamWaitEvent(s1, evFork, 0);

    // branch B (side stream): CSR-by-dst build — hidden under the GEMM
    hist_kernel<<<eg, 256, 0, s1>>>(ei);
    scan1_kernel<<<SCAN_B, 256, 0, s1>>>();
    scan2_kernel<<<1, 256, 0, s1>>>();
    scan3_kernel<<<SCAN_B, 256, 0, s1>>>();
    scatter_kernel<<<eg, 256, 0, s1>>>(ei, etype);
    cudaEventRecord(evJoin, s1);

    // branch A (main stream): fp16 prep + GEMM (launch index 3 = gemm for ncu)
    prep_convert_kernel<<<prep_grid, 256>>>(relW, w_self, x);
    dim3 ggrid(GROUPS, N_RELS);
    gemm_kernel<<<ggrid, 256, GEMM_SMEM>>>(relB, b_self);

    // join, then gather + segment-sum + LayerNorm
    cudaStreamWaitEvent(0, evJoin, 0);
    final_kernel<<<(N_NODES * 32 + 255) / 256, 256>>>(gamma, beta, out);
}